// round 13
// baseline (speedup 1.0000x reference)
#include <cuda_runtime.h>
#include <cuda_bf16.h>
#include <mma.h>
#include <math.h>
#include <stdint.h>

using namespace nvcuda;

#define NP     1024
#define EMBD   64
#define HID    128
#define NCELL  64
#define PN     4096     // NCELL * EMBD
#define NGATE  512
#define MIX    20
#define NOUT   120

// ---------------- device scratch (static, no allocations) ----------------
__device__ float g_P[NP * PN];        // 16 MB
__device__ float g_gates[NP * NGATE]; // 2 MB: partial gates ([emb|h0] part + biases)
__device__ float g_pool[NP * EMBD];   // 256 KB
__device__ float g_h[NP * HID];       // 0.5 MB
__device__ int   g_slist[NP * NP];    // 4 MB
__device__ int   g_scnt[NP];

__device__ __forceinline__ float sigm(float x) { return 1.0f / (1.0f + expf(-x)); }

#define PDL_TRIGGER() asm volatile("griddepcontrol.launch_dependents;" ::: "memory")
#define PDL_WAIT()    asm volatile("griddepcontrol.wait;" ::: "memory")

// split one float4 into hi/lo bf16x2 pairs and store to smem
__device__ __forceinline__ void split_store(__nv_bfloat16* d1, __nv_bfloat16* d2, float4 v) {
    __nv_bfloat162 h1a, h1b, h2a, h2b;
    h1a.x = __float2bfloat16(v.x); h2a.x = __float2bfloat16(v.x - __bfloat162float(h1a.x));
    h1a.y = __float2bfloat16(v.y); h2a.y = __float2bfloat16(v.y - __bfloat162float(h1a.y));
    h1b.x = __float2bfloat16(v.z); h2b.x = __float2bfloat16(v.z - __bfloat162float(h1b.x));
    h1b.y = __float2bfloat16(v.w); h2b.y = __float2bfloat16(v.w - __bfloat162float(h1b.y));
    *(__nv_bfloat162*)(d1)     = h1a;
    *(__nv_bfloat162*)(d1 + 2) = h1b;
    *(__nv_bfloat162*)(d2)     = h2a;
    *(__nv_bfloat162*)(d2 + 2) = h2b;
}
__device__ __forceinline__ void split_store1(__nv_bfloat16* d1, __nv_bfloat16* d2, float v) {
    const __nv_bfloat16 h1 = __float2bfloat16(v);
    *d1 = h1;
    *d2 = __float2bfloat16(v - __bfloat162float(h1));
}

// ============ K0: classify pairs (runs under mma_P / gates_pre) ============
__global__ __launch_bounds__(256) void classify_kernel(const float* __restrict__ xabs) {
    __shared__ float sx[NP];
    __shared__ float sy[NP];
    __shared__ int   wcnt[8];

    const int n = blockIdx.x;
    const int t = threadIdx.x;
    const int w = t >> 5;
    const int lane = t & 31;

    if (t == 0) PDL_TRIGGER();

    for (int i = t; i < NP; i += 256) {
        const float2 v = ((const float2*)xabs)[i];
        sx[i] = v.x;
        sy[i] = v.y;
    }
    __syncthreads();

    const float wl = sx[n] - 0.2f;
    const float bl = sy[n] - 0.2f;

    int cells[4];
    unsigned masks[4];
    int cnt = 0;
    #pragma unroll
    for (int j = 0; j < 4; j++) {
        const int m = w * 128 + j * 32 + lane;
        const float dx = sx[m] - wl;
        const float dy = sy[m] - bl;
        int cell = -1;
        if (dx >= 0.0f && dx < 0.4f && dy >= 0.0f && dy < 0.4f && m != n) {
            const int cx = (int)floorf(__fmul_rn(__fdiv_rn(dx, 0.4f), 8.0f));
            const int cy = (int)floorf(__fmul_rn(__fdiv_rn(dy, 0.4f), 8.0f));
            if (cx >= 0 && cx < 8 && cy >= 0 && cy < 8) cell = cx + cy * 8;
        }
        cells[j] = (cell >= 0) ? (m * PN + cell * EMBD) : -1;
        masks[j] = __ballot_sync(0xFFFFFFFFu, cell >= 0);
        cnt += __popc(masks[j]);
    }
    if (lane == 0) wcnt[w] = cnt;
    __syncthreads();

    int base = 0, tot = 0;
    #pragma unroll
    for (int ww = 0; ww < 8; ww++) {
        if (ww < w) base += wcnt[ww];
        tot += wcnt[ww];
    }
    int* lst = g_slist + n * NP;
    #pragma unroll
    for (int j = 0; j < 4; j++) {
        if (cells[j] >= 0)
            lst[base + __popc(masks[j] & ((1u << lane) - 1u))] = cells[j];
        base += __popc(masks[j]);
    }
    if (t == 0) g_scnt[n] = tot;
}

// ============ K1: gates_pre — [emb|h0] @ W^T + biases (K=192, independent) ============
#define KPRE  192
#define LDPRE 200
#define TILEPRE (64 * LDPRE)
#define SMEM_PRE_BYTES (4 * TILEPRE * 2 + 64 * 68 * 4)

__global__ __launch_bounds__(256, 1) void gates_pre_kernel(const float* __restrict__ xabs,
                                                           const float* __restrict__ h0,
                                                           const float* __restrict__ W_emb,
                                                           const float* __restrict__ b_emb,
                                                           const float* __restrict__ W_ih,
                                                           const float* __restrict__ W_hh,
                                                           const float* __restrict__ b_ih,
                                                           const float* __restrict__ b_hh) {
    extern __shared__ __align__(16) __nv_bfloat16 smemQ[];
    __nv_bfloat16* sA1 = smemQ;
    __nv_bfloat16* sA2 = smemQ + TILEPRE;
    __nv_bfloat16* sB1 = smemQ + 2 * TILEPRE;
    __nv_bfloat16* sB2 = smemQ + 3 * TILEPRE;
    float* sg = (float*)(smemQ + 4 * TILEPRE);   // [64][68]

    const int row0 = blockIdx.x * 64;
    const int d0   = blockIdx.y * 16;
    const int t   = threadIdx.x;
    const int wid = t >> 5;
    const int warp_m = wid & 3;
    const int warp_n = wid >> 2;

    if (t == 0) PDL_TRIGGER();

    // A = [emb(computed inline) | h0]
    for (int i = t; i < 64 * KPRE; i += 256) {
        const int row = i / KPRE;
        const int k   = i - row * KPRE;
        const int n = row0 + row;
        float v;
        if (k < 64) {
            const float2 x = ((const float2*)xabs)[n];
            v = fmaxf(x.x * W_emb[2 * k] + x.y * W_emb[2 * k + 1] + b_emb[k], 0.0f);
        } else {
            v = h0[n * HID + (k - 64)];
        }
        split_store1(sA1 + row * LDPRE + k, sA2 + row * LDPRE + k, v);
    }
    // B: k<64 -> W_ih[:, 0:64] (emb cols), k>=64 -> W_hh (h0)
    for (int i = t; i < 64 * KPRE; i += 256) {
        const int cc = i / KPRE;
        const int k  = i - cc * KPRE;
        const int wrow = (cc >> 4) * 128 + d0 + (cc & 15);
        const float v = (k < 64) ? W_ih[wrow * 128 + k] : W_hh[wrow * 128 + (k - 64)];
        split_store1(sB1 + cc * LDPRE + k, sB2 + cc * LDPRE + k, v);
    }
    __syncthreads();

    wmma::fragment<wmma::accumulator, 16, 16, 16, float> acc[2];
    wmma::fill_fragment(acc[0], 0.0f);
    wmma::fill_fragment(acc[1], 0.0f);
    wmma::fragment<wmma::matrix_a, 16, 16, 16, __nv_bfloat16, wmma::row_major> af;
    wmma::fragment<wmma::matrix_b, 16, 16, 16, __nv_bfloat16, wmma::col_major> bf[2];

    #pragma unroll
    for (int term = 0; term < 3; term++) {
        const __nv_bfloat16* sA = (term == 1) ? sA2 : sA1;
        const __nv_bfloat16* sB = (term == 2) ? sB2 : sB1;
        #pragma unroll
        for (int k0 = 0; k0 < KPRE / 16; k0++) {
            wmma::load_matrix_sync(af, sA + (warp_m * 16) * LDPRE + k0 * 16, LDPRE);
            #pragma unroll
            for (int j = 0; j < 2; j++) {
                wmma::load_matrix_sync(bf[j], sB + (warp_n * 32 + j * 16) * LDPRE + k0 * 16, LDPRE);
                wmma::mma_sync(acc[j], af, bf[j], acc[j]);
            }
        }
    }

    #pragma unroll
    for (int j = 0; j < 2; j++)
        wmma::store_matrix_sync(sg + (warp_m * 16) * 68 + warp_n * 32 + j * 16,
                                acc[j], 68, wmma::mem_row_major);
    __syncthreads();

    #pragma unroll
    for (int idx = t; idx < 4096; idx += 256) {
        const int rl = idx >> 6;
        const int cc = idx & 63;
        const int g  = (cc >> 4) * 128 + d0 + (cc & 15);
        g_gates[(row0 + rl) * NGATE + g] = sg[rl * 68 + cc] + b_ih[g] + b_hh[g];
    }

    PDL_WAIT();   // completion-ordering: classify finished before this kernel completes
}

// ============ K2: WMMA bf16 P-GEMM (validated R7 body) ============
#define LDP 136
#define TILEP (128 * LDP)
#define SMEM_P_BYTES (4 * TILEP * 2)

__global__ __launch_bounds__(256, 1) void mma_P_kernel(const float* __restrict__ h0,
                                                       const float* __restrict__ Wsoc) {
    extern __shared__ __align__(16) __nv_bfloat16 smemP[];
    __nv_bfloat16* sA1 = smemP;
    __nv_bfloat16* sA2 = smemP + TILEP;
    __nv_bfloat16* sB1 = smemP + 2 * TILEP;
    __nv_bfloat16* sB2 = smemP + 3 * TILEP;

    const int t   = threadIdx.x;
    const int wid = t >> 5;
    const int warp_m = wid & 1;
    const int warp_n = wid >> 1;
    const int row0 = blockIdx.x * 128;
    const int col0 = blockIdx.y * 128;

    if (t == 0) PDL_TRIGGER();

    #pragma unroll
    for (int i = t; i < 4096; i += 256) {
        const int row = i >> 5, k4 = i & 31;
        const float4 v = *(const float4*)&h0[(row0 + row) * HID + k4 * 4];
        split_store(sA1 + row * LDP + k4 * 4, sA2 + row * LDP + k4 * 4, v);
    }
    #pragma unroll
    for (int i = t; i < 4096; i += 256) {
        const int row = i >> 5, k4 = i & 31;
        const int ce = col0 + row;
        const int e = ce & 63, c = ce >> 6;
        const float4 v = *(const float4*)&Wsoc[e * (NCELL * HID) + c * HID + k4 * 4];
        split_store(sB1 + row * LDP + k4 * 4, sB2 + row * LDP + k4 * 4, v);
    }
    __syncthreads();

    wmma::fragment<wmma::accumulator, 16, 16, 16, float> acc[4][2];
    #pragma unroll
    for (int i = 0; i < 4; i++)
        #pragma unroll
        for (int j = 0; j < 2; j++)
            wmma::fill_fragment(acc[i][j], 0.0f);

    wmma::fragment<wmma::matrix_a, 16, 16, 16, __nv_bfloat16, wmma::row_major> af;
    wmma::fragment<wmma::matrix_b, 16, 16, 16, __nv_bfloat16, wmma::col_major> bf[2];

    #pragma unroll
    for (int term = 0; term < 3; term++) {
        const __nv_bfloat16* sA = (term == 1) ? sA2 : sA1;
        const __nv_bfloat16* sB = (term == 2) ? sB2 : sB1;
        #pragma unroll
        for (int k0 = 0; k0 < 8; k0++) {
            #pragma unroll
            for (int j = 0; j < 2; j++)
                wmma::load_matrix_sync(bf[j], sB + (warp_n * 32 + j * 16) * LDP + k0 * 16, LDP);
            #pragma unroll
            for (int i = 0; i < 4; i++) {
                wmma::load_matrix_sync(af, sA + (warp_m * 64 + i * 16) * LDP + k0 * 16, LDP);
                wmma::mma_sync(acc[i][0], af, bf[0], acc[i][0]);
                wmma::mma_sync(acc[i][1], af, bf[1], acc[i][1]);
            }
        }
    }

    #pragma unroll
    for (int i = 0; i < 4; i++)
        #pragma unroll
        for (int j = 0; j < 2; j++) {
            float* dst = g_P + (size_t)(row0 + warp_m * 64 + i * 16) * PN
                             + col0 + warp_n * 32 + j * 16;
            wmma::store_matrix_sync(dst, acc[i][j], PN, wmma::mem_row_major);
        }

    PDL_WAIT();   // completion-ordering: gates_pre (and transitively classify) done
}

// ============ K3: pure gather -> g_pool ============
__global__ __launch_bounds__(256) void gather_kernel(const float* __restrict__ b_soc) {
    __shared__ int   slist[NP];
    __shared__ float sred[4][64];

    const int n = blockIdx.x;
    const int t = threadIdx.x;

    if (t == 0) PDL_TRIGGER();

    PDL_WAIT();   // g_P + (transitively) g_slist complete

    const int tot = g_scnt[n];
    for (int i = t; i < tot; i += 256) slist[i] = g_slist[n * NP + i];
    __syncthreads();

    const int slot = t >> 6;
    const int e    = t & 63;
    float a0 = 0.0f, a1 = 0.0f, a2 = 0.0f, a3 = 0.0f;
    int i = slot;
    for (; i + 16 <= tot; i += 16) {
        a0 += g_P[(size_t)slist[i]      + e];
        a1 += g_P[(size_t)slist[i + 4]  + e];
        a2 += g_P[(size_t)slist[i + 8]  + e];
        a3 += g_P[(size_t)slist[i + 12] + e];
    }
    for (; i < tot; i += 4) a0 += g_P[(size_t)slist[i] + e];
    sred[slot][e] = (a0 + a1) + (a2 + a3);
    __syncthreads();

    if (t < 64) {
        const float s = sred[0][e] + sred[1][e] + sred[2][e] + sred[3][e] + b_soc[e];
        g_pool[n * EMBD + e] = fmaxf(s, 0.0f);
    }
}

// ============ K4: gates_post — pool @ W_ih[:,64:128]^T (K=64) + partial + LSTM ============
#define LDQ 72
#define TILEQ (64 * LDQ)
#define SMEM_Q_BYTES (4 * TILEQ * 2 + 64 * 68 * 4)

__global__ __launch_bounds__(256, 1) void gates_post_kernel(const float* __restrict__ W_ih,
                                                            const float* __restrict__ c0) {
    extern __shared__ __align__(16) __nv_bfloat16 smemR[];
    __nv_bfloat16* sA1 = smemR;
    __nv_bfloat16* sA2 = smemR + TILEQ;
    __nv_bfloat16* sB1 = smemR + 2 * TILEQ;
    __nv_bfloat16* sB2 = smemR + 3 * TILEQ;
    float* sg = (float*)(smemR + 4 * TILEQ);   // [64][68]

    const int row0 = blockIdx.x * 64;
    const int d0   = blockIdx.y * 16;
    const int t   = threadIdx.x;
    const int wid = t >> 5;
    const int warp_m = wid & 3;
    const int warp_n = wid >> 2;

    if (t == 0) PDL_TRIGGER();

    // independent prologue: W_ih pool columns (64..127)
    #pragma unroll
    for (int i = t; i < 4096; i += 256) {
        const int cc = i >> 6, k = i & 63;
        const int wrow = (cc >> 4) * 128 + d0 + (cc & 15);
        split_store1(sB1 + cc * LDQ + k, sB2 + cc * LDQ + k, W_ih[wrow * 128 + 64 + k]);
    }

    PDL_WAIT();   // g_pool complete (and transitively g_gates)

    #pragma unroll
    for (int i = t; i < 1024; i += 256) {
        const int row = i >> 4, k4 = i & 15;
        const float4 v = *(const float4*)&g_pool[(row0 + row) * EMBD + k4 * 4];
        split_store(sA1 + row * LDQ + k4 * 4, sA2 + row * LDQ + k4 * 4, v);
    }
    __syncthreads();

    wmma::fragment<wmma::accumulator, 16, 16, 16, float> acc[2];
    wmma::fill_fragment(acc[0], 0.0f);
    wmma::fill_fragment(acc[1], 0.0f);
    wmma::fragment<wmma::matrix_a, 16, 16, 16, __nv_bfloat16, wmma::row_major> af;
    wmma::fragment<wmma::matrix_b, 16, 16, 16, __nv_bfloat16, wmma::col_major> bf[2];

    #pragma unroll
    for (int term = 0; term < 3; term++) {
        const __nv_bfloat16* sA = (term == 1) ? sA2 : sA1;
        const __nv_bfloat16* sB = (term == 2) ? sB2 : sB1;
        #pragma unroll
        for (int k0 = 0; k0 < 4; k0++) {
            wmma::load_matrix_sync(af, sA + (warp_m * 16) * LDQ + k0 * 16, LDQ);
            #pragma unroll
            for (int j = 0; j < 2; j++) {
                wmma::load_matrix_sync(bf[j], sB + (warp_n * 32 + j * 16) * LDQ + k0 * 16, LDQ);
                wmma::mma_sync(acc[j], af, bf[j], acc[j]);
            }
        }
    }

    #pragma unroll
    for (int j = 0; j < 2; j++)
        wmma::store_matrix_sync(sg + (warp_m * 16) * 68 + warp_n * 32 + j * 16,
                                acc[j], 68, wmma::mem_row_major);
    __syncthreads();

    // combine with precomputed partial (includes biases) + LSTM
    #pragma unroll
    for (int idx = t; idx < 1024; idx += 256) {
        const int rl = idx >> 4;
        const int dd = idx & 15;
        const int d = d0 + dd;
        const int n = row0 + rl;
        const float* gp = g_gates + n * NGATE;
        const float ig = sg[rl * 68 + dd]      + gp[d];
        const float fg = sg[rl * 68 + 16 + dd] + gp[128 + d];
        const float gg = sg[rl * 68 + 32 + dd] + gp[256 + d];
        const float og = sg[rl * 68 + 48 + dd] + gp[384 + d];
        const float c = sigm(fg) * c0[n * HID + d] + sigm(ig) * tanhf(gg);
        g_h[n * HID + d] = sigm(og) * tanhf(c);
    }
}

// ============ K5: WMMA output projection (validated body) ============
#define LDO 136

__global__ __launch_bounds__(256) void out_kernel(const float* __restrict__ W_out,
                                                  const float* __restrict__ b_out,
                                                  float* __restrict__ out) {
    __shared__ __align__(16) __nv_bfloat16 sA1[16 * LDO];
    __shared__ __align__(16) __nv_bfloat16 sA2[16 * LDO];
    __shared__ __align__(16) __nv_bfloat16 sB1[64 * LDO];
    __shared__ __align__(16) __nv_bfloat16 sB2[64 * LDO];
    __shared__ float so[16 * 68];

    const int row0 = blockIdx.x * 16;
    const int col0 = blockIdx.y * 64;
    const int t   = threadIdx.x;
    const int wid = t >> 5;

    #pragma unroll
    for (int i = t; i < 2048; i += 256) {
        const int ee = i >> 5, k4 = i & 31;
        const int eg = col0 + ee;
        const float4 v = (eg < NOUT) ? *(const float4*)&W_out[eg * HID + k4 * 4]
                                     : make_float4(0.f, 0.f, 0.f, 0.f);
        split_store(sB1 + ee * LDO + k4 * 4, sB2 + ee * LDO + k4 * 4, v);
    }

    PDL_WAIT();

    #pragma unroll
    for (int i = t; i < 512; i += 256) {
        const int row = i >> 5, k4 = i & 31;
        const float4 v = *(const float4*)&g_h[(row0 + row) * HID + k4 * 4];
        split_store(sA1 + row * LDO + k4 * 4, sA2 + row * LDO + k4 * 4, v);
    }
    __syncthreads();

    if (wid < 4) {
        wmma::fragment<wmma::accumulator, 16, 16, 16, float> acc;
        wmma::fill_fragment(acc, 0.0f);
        wmma::fragment<wmma::matrix_a, 16, 16, 16, __nv_bfloat16, wmma::row_major> af;
        wmma::fragment<wmma::matrix_b, 16, 16, 16, __nv_bfloat16, wmma::col_major> bf;
        #pragma unroll
        for (int term = 0; term < 3; term++) {
            const __nv_bfloat16* sA = (term == 1) ? sA2 : sA1;
            const __nv_bfloat16* sB = (term == 2) ? sB2 : sB1;
            #pragma unroll
            for (int k0 = 0; k0 < 8; k0++) {
                wmma::load_matrix_sync(af, sA + k0 * 16, LDO);
                wmma::load_matrix_sync(bf, sB + (wid * 16) * LDO + k0 * 16, LDO);
                wmma::mma_sync(acc, af, bf, acc);
            }
        }
        wmma::store_matrix_sync(so + wid * 16, acc, 68, wmma::mem_row_major);
    }
    __syncthreads();

    #pragma unroll
    for (int idx = t; idx < 16 * 64; idx += 256) {
        const int r  = idx >> 6;
        const int cc = idx & 63;
        const int e  = col0 + cc;
        if (e < NOUT) {
            const float v = so[r * 68 + cc] + b_out[e];
            out[(e / MIX) * (NP * MIX) + (row0 + r) * MIX + (e % MIX)] = v;
        }
    }
}

// ---------------- launch ----------------
extern "C" void kernel_launch(void* const* d_in, const int* in_sizes, int n_in,
                              void* d_out, int out_size) {
    const float* xabs  = (const float*)d_in[0];
    const float* h0    = (const float*)d_in[1];
    const float* c0    = (const float*)d_in[2];
    const float* W_emb = (const float*)d_in[3];
    const float* b_emb = (const float*)d_in[4];
    const float* W_soc = (const float*)d_in[5];
    const float* b_soc = (const float*)d_in[6];
    const float* W_ih  = (const float*)d_in[7];
    const float* W_hh  = (const float*)d_in[8];
    const float* b_ih  = (const float*)d_in[9];
    const float* b_hh  = (const float*)d_in[10];
    const float* W_out = (const float*)d_in[11];
    const float* b_out = (const float*)d_in[12];
    float* out = (float*)d_out;

    cudaFuncSetAttribute(mma_P_kernel, cudaFuncAttributeMaxDynamicSharedMemorySize, SMEM_P_BYTES);
    cudaFuncSetAttribute(gates_pre_kernel, cudaFuncAttributeMaxDynamicSharedMemorySize, SMEM_PRE_BYTES);
    cudaFuncSetAttribute(gates_post_kernel, cudaFuncAttributeMaxDynamicSharedMemorySize, SMEM_Q_BYTES);

    cudaLaunchAttribute attrs[1];
    attrs[0].id = cudaLaunchAttributeProgrammaticStreamSerialization;
    attrs[0].val.programmaticStreamSerializationAllowed = 1;

    // K0: classify (head, normal launch)
    classify_kernel<<<NP, 256>>>(xabs);

    // K1: gates_pre — independent, overlaps classify
    {
        cudaLaunchConfig_t cfg = {};
        cfg.gridDim = dim3(16, 8, 1);
        cfg.blockDim = dim3(256, 1, 1);
        cfg.dynamicSmemBytes = SMEM_PRE_BYTES;
        cfg.stream = 0;
        cfg.attrs = attrs;
        cfg.numAttrs = 1;
        cudaLaunchKernelEx(&cfg, gates_pre_kernel, xabs, h0, W_emb, b_emb, W_ih, W_hh, b_ih, b_hh);
    }
    // K2: mma_P — independent, overlaps gates_pre
    {
        cudaLaunchConfig_t cfg = {};
        cfg.gridDim = dim3(8, 32, 1);
        cfg.blockDim = dim3(256, 1, 1);
        cfg.dynamicSmemBytes = SMEM_P_BYTES;
        cfg.stream = 0;
        cfg.attrs = attrs;
        cfg.numAttrs = 1;
        cudaLaunchKernelEx(&cfg, mma_P_kernel, h0, W_soc);
    }
    // K3: gather
    {
        cudaLaunchConfig_t cfg = {};
        cfg.gridDim = dim3(NP, 1, 1);
        cfg.blockDim = dim3(256, 1, 1);
        cfg.dynamicSmemBytes = 0;
        cfg.stream = 0;
        cfg.attrs = attrs;
        cfg.numAttrs = 1;
        cudaLaunchKernelEx(&cfg, gather_kernel, b_soc);
    }
    // K4: gates_post + LSTM
    {
        cudaLaunchConfig_t cfg = {};
        cfg.gridDim = dim3(16, 8, 1);
        cfg.blockDim = dim3(256, 1, 1);
        cfg.dynamicSmemBytes = SMEM_Q_BYTES;
        cfg.stream = 0;
        cfg.attrs = attrs;
        cfg.numAttrs = 1;
        cudaLaunchKernelEx(&cfg, gates_post_kernel, W_ih, c0);
    }
    // K5: output projection
    {
        cudaLaunchConfig_t cfg = {};
        cfg.gridDim = dim3(64, 2, 1);
        cfg.blockDim = dim3(256, 1, 1);
        cfg.dynamicSmemBytes = 0;
        cfg.stream = 0;
        cfg.attrs = attrs;
        cfg.numAttrs = 1;
        cudaLaunchKernelEx(&cfg, out_kernel, W_out, b_out, out);
    }
}

// round 14
// speedup vs baseline: 1.1472x; 1.1472x over previous
#include <cuda_runtime.h>
#include <cuda_bf16.h>
#include <mma.h>
#include <math.h>
#include <stdint.h>

using namespace nvcuda;

#define NP     1024
#define EMBD   64
#define HID    128
#define NCELL  64
#define PN     4096     // NCELL * EMBD
#define NGATE  512
#define MIX    20
#define NOUT   120

// ---------------- device scratch (static, no allocations) ----------------
__device__ float g_P[NP * PN];        // 16 MB
__device__ float g_gates[NP * NGATE]; // 2 MB: partial gates ([emb|h0] + biases)
__device__ float g_pool[NP * EMBD];   // 256 KB
__device__ float g_h[NP * HID];       // 0.5 MB

__device__ __forceinline__ float sigm(float x) { return 1.0f / (1.0f + expf(-x)); }

#define PDL_TRIGGER() asm volatile("griddepcontrol.launch_dependents;" ::: "memory")
#define PDL_WAIT()    asm volatile("griddepcontrol.wait;" ::: "memory")

__device__ __forceinline__ void split_store(__nv_bfloat16* d1, __nv_bfloat16* d2, float4 v) {
    __nv_bfloat162 h1a, h1b, h2a, h2b;
    h1a.x = __float2bfloat16(v.x); h2a.x = __float2bfloat16(v.x - __bfloat162float(h1a.x));
    h1a.y = __float2bfloat16(v.y); h2a.y = __float2bfloat16(v.y - __bfloat162float(h1a.y));
    h1b.x = __float2bfloat16(v.z); h2b.x = __float2bfloat16(v.z - __bfloat162float(h1b.x));
    h1b.y = __float2bfloat16(v.w); h2b.y = __float2bfloat16(v.w - __bfloat162float(h1b.y));
    *(__nv_bfloat162*)(d1)     = h1a;
    *(__nv_bfloat162*)(d1 + 2) = h1b;
    *(__nv_bfloat162*)(d2)     = h2a;
    *(__nv_bfloat162*)(d2 + 2) = h2b;
}
__device__ __forceinline__ void split_store1(__nv_bfloat16* d1, __nv_bfloat16* d2, float v) {
    const __nv_bfloat16 h1 = __float2bfloat16(v);
    *d1 = h1;
    *d2 = __float2bfloat16(v - __bfloat162float(h1));
}

// ============ K1: WMMA bf16 P-GEMM (validated 39.4us body) ============
#define LDP 136
#define TILEP (128 * LDP)
#define SMEM_P_BYTES (4 * TILEP * 2)

__global__ __launch_bounds__(256, 1) void mma_P_kernel(const float* __restrict__ h0,
                                                       const float* __restrict__ Wsoc) {
    extern __shared__ __align__(16) __nv_bfloat16 smemP[];
    __nv_bfloat16* sA1 = smemP;
    __nv_bfloat16* sA2 = smemP + TILEP;
    __nv_bfloat16* sB1 = smemP + 2 * TILEP;
    __nv_bfloat16* sB2 = smemP + 3 * TILEP;

    const int t   = threadIdx.x;
    const int wid = t >> 5;
    const int warp_m = wid & 1;
    const int warp_n = wid >> 1;
    const int row0 = blockIdx.x * 128;
    const int col0 = blockIdx.y * 128;

    if (t == 0) PDL_TRIGGER();

    #pragma unroll
    for (int i = t; i < 4096; i += 256) {
        const int row = i >> 5, k4 = i & 31;
        const float4 v = *(const float4*)&h0[(row0 + row) * HID + k4 * 4];
        split_store(sA1 + row * LDP + k4 * 4, sA2 + row * LDP + k4 * 4, v);
    }
    #pragma unroll
    for (int i = t; i < 4096; i += 256) {
        const int row = i >> 5, k4 = i & 31;
        const int ce = col0 + row;
        const int e = ce & 63, c = ce >> 6;
        const float4 v = *(const float4*)&Wsoc[e * (NCELL * HID) + c * HID + k4 * 4];
        split_store(sB1 + row * LDP + k4 * 4, sB2 + row * LDP + k4 * 4, v);
    }
    __syncthreads();

    wmma::fragment<wmma::accumulator, 16, 16, 16, float> acc[4][2];
    #pragma unroll
    for (int i = 0; i < 4; i++)
        #pragma unroll
        for (int j = 0; j < 2; j++)
            wmma::fill_fragment(acc[i][j], 0.0f);

    wmma::fragment<wmma::matrix_a, 16, 16, 16, __nv_bfloat16, wmma::row_major> af;
    wmma::fragment<wmma::matrix_b, 16, 16, 16, __nv_bfloat16, wmma::col_major> bf[2];

    #pragma unroll
    for (int term = 0; term < 3; term++) {
        const __nv_bfloat16* sA = (term == 1) ? sA2 : sA1;
        const __nv_bfloat16* sB = (term == 2) ? sB2 : sB1;
        #pragma unroll
        for (int k0 = 0; k0 < 8; k0++) {
            #pragma unroll
            for (int j = 0; j < 2; j++)
                wmma::load_matrix_sync(bf[j], sB + (warp_n * 32 + j * 16) * LDP + k0 * 16, LDP);
            #pragma unroll
            for (int i = 0; i < 4; i++) {
                wmma::load_matrix_sync(af, sA + (warp_m * 64 + i * 16) * LDP + k0 * 16, LDP);
                wmma::mma_sync(acc[i][0], af, bf[0], acc[i][0]);
                wmma::mma_sync(acc[i][1], af, bf[1], acc[i][1]);
            }
        }
    }

    #pragma unroll
    for (int i = 0; i < 4; i++)
        #pragma unroll
        for (int j = 0; j < 2; j++) {
            float* dst = g_P + (size_t)(row0 + warp_m * 64 + i * 16) * PN
                             + col0 + warp_n * 32 + j * 16;
            wmma::store_matrix_sync(dst, acc[i][j], PN, wmma::mem_row_major);
        }
}

// ============ K2: merged classify + gather (R11 structure, 512 thr) -> g_pool ============
__global__ __launch_bounds__(512) void scatter_kernel(const float* __restrict__ xabs,
                                                      const float* __restrict__ b_soc) {
    __shared__ float sx[NP];
    __shared__ float sy[NP];
    __shared__ int   slist[NP];
    __shared__ int   wcnt[16];
    __shared__ float sred[8][64];

    const int n = blockIdx.x;
    const int t = threadIdx.x;
    const int w = t >> 5;
    const int lane = t & 31;

    if (t == 0) PDL_TRIGGER();

    for (int i = t; i < NP; i += 512) {
        const float2 v = ((const float2*)xabs)[i];
        sx[i] = v.x;
        sy[i] = v.y;
    }
    __syncthreads();

    const float wl = sx[n] - 0.2f;
    const float bl = sy[n] - 0.2f;

    int cells[2];
    unsigned masks[2];
    int cnt = 0;
    #pragma unroll
    for (int j = 0; j < 2; j++) {
        const int m = w * 64 + j * 32 + lane;
        const float dx = sx[m] - wl;
        const float dy = sy[m] - bl;
        int cell = -1;
        if (dx >= 0.0f && dx < 0.4f && dy >= 0.0f && dy < 0.4f && m != n) {
            const int cx = (int)floorf(__fmul_rn(__fdiv_rn(dx, 0.4f), 8.0f));
            const int cy = (int)floorf(__fmul_rn(__fdiv_rn(dy, 0.4f), 8.0f));
            if (cx >= 0 && cx < 8 && cy >= 0 && cy < 8) cell = cx + cy * 8;
        }
        cells[j] = (cell >= 0) ? (m * PN + cell * EMBD) : -1;
        masks[j] = __ballot_sync(0xFFFFFFFFu, cell >= 0);
        cnt += __popc(masks[j]);
    }
    if (lane == 0) wcnt[w] = cnt;
    __syncthreads();

    int base = 0, tot = 0;
    #pragma unroll
    for (int ww = 0; ww < 16; ww++) {
        if (ww < w) base += wcnt[ww];
        tot += wcnt[ww];
    }
    #pragma unroll
    for (int j = 0; j < 2; j++) {
        if (cells[j] >= 0)
            slist[base + __popc(masks[j] & ((1u << lane) - 1u))] = cells[j];
        base += __popc(masks[j]);
    }
    __syncthreads();

    PDL_WAIT();   // g_P complete

    // gather: 8 slots x 64 e, 4 independent chains
    const int slot = t >> 6;
    const int e    = t & 63;
    float a0 = 0.0f, a1 = 0.0f, a2 = 0.0f, a3 = 0.0f;
    int i = slot;
    for (; i + 32 <= tot; i += 32) {
        a0 += g_P[(size_t)slist[i]      + e];
        a1 += g_P[(size_t)slist[i + 8]  + e];
        a2 += g_P[(size_t)slist[i + 16] + e];
        a3 += g_P[(size_t)slist[i + 24] + e];
    }
    for (; i < tot; i += 8) a0 += g_P[(size_t)slist[i] + e];
    sred[slot][e] = (a0 + a1) + (a2 + a3);
    __syncthreads();

    if (t < 64) {
        float s = b_soc[e];
        #pragma unroll
        for (int sl = 0; sl < 8; sl++) s += sred[sl][e];
        g_pool[n * EMBD + e] = fmaxf(s, 0.0f);
    }
}

// ============ K3: gates_pre — [emb|h0]@W^T + biases (K=192, K-chunked, 54KB smem) ============
// NO leading wait (inputs only) — runs concurrent with scatter's gather phase.
// Trailing PDL_WAIT preserves stream-completion ordering for gates_post.
#define LDQ 72
#define TILEQ (64 * LDQ)

__global__ __launch_bounds__(256) void gates_pre_kernel(const float* __restrict__ xabs,
                                                        const float* __restrict__ h0,
                                                        const float* __restrict__ W_emb,
                                                        const float* __restrict__ b_emb,
                                                        const float* __restrict__ W_ih,
                                                        const float* __restrict__ W_hh,
                                                        const float* __restrict__ b_ih,
                                                        const float* __restrict__ b_hh) {
    __shared__ __align__(16) __nv_bfloat16 sA1[TILEQ];
    __shared__ __align__(16) __nv_bfloat16 sA2[TILEQ];
    __shared__ __align__(16) __nv_bfloat16 sB1[TILEQ];
    __shared__ __align__(16) __nv_bfloat16 sB2[TILEQ];
    __shared__ float sg[64 * 68];

    const int row0 = blockIdx.x * 64;
    const int d0   = blockIdx.y * 16;
    const int t   = threadIdx.x;
    const int wid = t >> 5;
    const int warp_m = wid & 3;
    const int warp_n = wid >> 2;

    if (t == 0) PDL_TRIGGER();

    wmma::fragment<wmma::accumulator, 16, 16, 16, float> acc[2];
    wmma::fill_fragment(acc[0], 0.0f);
    wmma::fill_fragment(acc[1], 0.0f);
    wmma::fragment<wmma::matrix_a, 16, 16, 16, __nv_bfloat16, wmma::row_major> af;
    wmma::fragment<wmma::matrix_b, 16, 16, 16, __nv_bfloat16, wmma::col_major> bf[2];

    #pragma unroll
    for (int chunk = 0; chunk < 3; chunk++) {
        if (chunk > 0) __syncthreads();   // protect buffer reuse
        // A chunk: chunk0 = emb (computed), chunk1/2 = h0 halves (coalesced float4)
        if (chunk == 0) {
            for (int i = t; i < 4096; i += 256) {
                const int row = i >> 6, k = i & 63;
                const float2 x = ((const float2*)xabs)[row0 + row];
                const float v = fmaxf(x.x * W_emb[2 * k] + x.y * W_emb[2 * k + 1] + b_emb[k], 0.0f);
                split_store1(sA1 + row * LDQ + k, sA2 + row * LDQ + k, v);
            }
        } else {
            #pragma unroll
            for (int i = t; i < 1024; i += 256) {
                const int row = i >> 4, k4 = i & 15;
                const float4 v = *(const float4*)&h0[(row0 + row) * HID + (chunk - 1) * 64 + k4 * 4];
                split_store(sA1 + row * LDQ + k4 * 4, sA2 + row * LDQ + k4 * 4, v);
            }
        }
        // B chunk: chunk0 = W_ih[:, 0:64], chunk1/2 = W_hh halves (coalesced float4)
        #pragma unroll
        for (int i = t; i < 1024; i += 256) {
            const int cc = i >> 4, k4 = i & 15;
            const int wrow = (cc >> 4) * 128 + d0 + (cc & 15);
            const float4 v = (chunk == 0)
                ? *(const float4*)&W_ih[wrow * 128 + k4 * 4]
                : *(const float4*)&W_hh[wrow * 128 + (chunk - 1) * 64 + k4 * 4];
            split_store(sB1 + cc * LDQ + k4 * 4, sB2 + cc * LDQ + k4 * 4, v);
        }
        __syncthreads();

        #pragma unroll
        for (int term = 0; term < 3; term++) {
            const __nv_bfloat16* sA = (term == 1) ? sA2 : sA1;
            const __nv_bfloat16* sB = (term == 2) ? sB2 : sB1;
            #pragma unroll
            for (int k0 = 0; k0 < 4; k0++) {
                wmma::load_matrix_sync(af, sA + (warp_m * 16) * LDQ + k0 * 16, LDQ);
                #pragma unroll
                for (int j = 0; j < 2; j++) {
                    wmma::load_matrix_sync(bf[j], sB + (warp_n * 32 + j * 16) * LDQ + k0 * 16, LDQ);
                    wmma::mma_sync(acc[j], af, bf[j], acc[j]);
                }
            }
        }
    }
    __syncthreads();

    #pragma unroll
    for (int j = 0; j < 2; j++)
        wmma::store_matrix_sync(sg + (warp_m * 16) * 68 + warp_n * 32 + j * 16,
                                acc[j], 68, wmma::mem_row_major);
    __syncthreads();

    #pragma unroll
    for (int idx = t; idx < 4096; idx += 256) {
        const int rl = idx >> 6;
        const int cc = idx & 63;
        const int g  = (cc >> 4) * 128 + d0 + (cc & 15);
        g_gates[(row0 + rl) * NGATE + g] = sg[rl * 68 + cc] + b_ih[g] + b_hh[g];
    }

    PDL_WAIT();   // completion-ordering: don't finish before scatter (g_pool) finishes
}

// ============ K4: gates_post — pool @ W_ih[:,64:128]^T (K=64) + partial + LSTM ============
__global__ __launch_bounds__(256) void gates_post_kernel(const float* __restrict__ W_ih,
                                                         const float* __restrict__ c0) {
    __shared__ __align__(16) __nv_bfloat16 sA1[TILEQ];
    __shared__ __align__(16) __nv_bfloat16 sA2[TILEQ];
    __shared__ __align__(16) __nv_bfloat16 sB1[TILEQ];
    __shared__ __align__(16) __nv_bfloat16 sB2[TILEQ];
    __shared__ float sg[64 * 68];

    const int row0 = blockIdx.x * 64;
    const int d0   = blockIdx.y * 16;
    const int t   = threadIdx.x;
    const int wid = t >> 5;
    const int warp_m = wid & 3;
    const int warp_n = wid >> 2;

    if (t == 0) PDL_TRIGGER();

    // independent prologue: W_ih pool columns (64..127)
    #pragma unroll
    for (int i = t; i < 1024; i += 256) {
        const int cc = i >> 4, k4 = i & 15;
        const int wrow = (cc >> 4) * 128 + d0 + (cc & 15);
        const float4 v = *(const float4*)&W_ih[wrow * 128 + 64 + k4 * 4];
        split_store(sB1 + cc * LDQ + k4 * 4, sB2 + cc * LDQ + k4 * 4, v);
    }

    PDL_WAIT();   // gates_pre complete ⟹ (trailing wait) scatter complete ⟹ g_pool ready

    #pragma unroll
    for (int i = t; i < 1024; i += 256) {
        const int row = i >> 4, k4 = i & 15;
        const float4 v = *(const float4*)&g_pool[(row0 + row) * EMBD + k4 * 4];
        split_store(sA1 + row * LDQ + k4 * 4, sA2 + row * LDQ + k4 * 4, v);
    }
    __syncthreads();

    wmma::fragment<wmma::accumulator, 16, 16, 16, float> acc[2];
    wmma::fill_fragment(acc[0], 0.0f);
    wmma::fill_fragment(acc[1], 0.0f);
    wmma::fragment<wmma::matrix_a, 16, 16, 16, __nv_bfloat16, wmma::row_major> af;
    wmma::fragment<wmma::matrix_b, 16, 16, 16, __nv_bfloat16, wmma::col_major> bf[2];

    #pragma unroll
    for (int term = 0; term < 3; term++) {
        const __nv_bfloat16* sA = (term == 1) ? sA2 : sA1;
        const __nv_bfloat16* sB = (term == 2) ? sB2 : sB1;
        #pragma unroll
        for (int k0 = 0; k0 < 4; k0++) {
            wmma::load_matrix_sync(af, sA + (warp_m * 16) * LDQ + k0 * 16, LDQ);
            #pragma unroll
            for (int j = 0; j < 2; j++) {
                wmma::load_matrix_sync(bf[j], sB + (warp_n * 32 + j * 16) * LDQ + k0 * 16, LDQ);
                wmma::mma_sync(acc[j], af, bf[j], acc[j]);
            }
        }
    }

    #pragma unroll
    for (int j = 0; j < 2; j++)
        wmma::store_matrix_sync(sg + (warp_m * 16) * 68 + warp_n * 32 + j * 16,
                                acc[j], 68, wmma::mem_row_major);
    __syncthreads();

    #pragma unroll
    for (int idx = t; idx < 1024; idx += 256) {
        const int rl = idx >> 4;
        const int dd = idx & 15;
        const int d = d0 + dd;
        const int n = row0 + rl;
        const float* gp = g_gates + n * NGATE;
        const float ig = sg[rl * 68 + dd]      + gp[d];
        const float fg = sg[rl * 68 + 16 + dd] + gp[128 + d];
        const float gg = sg[rl * 68 + 32 + dd] + gp[256 + d];
        const float og = sg[rl * 68 + 48 + dd] + gp[384 + d];
        const float c = sigm(fg) * c0[n * HID + d] + sigm(ig) * tanhf(gg);
        g_h[n * HID + d] = sigm(og) * tanhf(c);
    }
}

// ============ K5: WMMA output projection (validated body) ============
#define LDO 136

__global__ __launch_bounds__(256) void out_kernel(const float* __restrict__ W_out,
                                                  const float* __restrict__ b_out,
                                                  float* __restrict__ out) {
    __shared__ __align__(16) __nv_bfloat16 sA1[16 * LDO];
    __shared__ __align__(16) __nv_bfloat16 sA2[16 * LDO];
    __shared__ __align__(16) __nv_bfloat16 sB1[64 * LDO];
    __shared__ __align__(16) __nv_bfloat16 sB2[64 * LDO];
    __shared__ float so[16 * 68];

    const int row0 = blockIdx.x * 16;
    const int col0 = blockIdx.y * 64;
    const int t   = threadIdx.x;
    const int wid = t >> 5;

    #pragma unroll
    for (int i = t; i < 2048; i += 256) {
        const int ee = i >> 5, k4 = i & 31;
        const int eg = col0 + ee;
        const float4 v = (eg < NOUT) ? *(const float4*)&W_out[eg * HID + k4 * 4]
                                     : make_float4(0.f, 0.f, 0.f, 0.f);
        split_store(sB1 + ee * LDO + k4 * 4, sB2 + ee * LDO + k4 * 4, v);
    }

    PDL_WAIT();

    #pragma unroll
    for (int i = t; i < 512; i += 256) {
        const int row = i >> 5, k4 = i & 31;
        const float4 v = *(const float4*)&g_h[(row0 + row) * HID + k4 * 4];
        split_store(sA1 + row * LDO + k4 * 4, sA2 + row * LDO + k4 * 4, v);
    }
    __syncthreads();

    if (wid < 4) {
        wmma::fragment<wmma::accumulator, 16, 16, 16, float> acc;
        wmma::fill_fragment(acc, 0.0f);
        wmma::fragment<wmma::matrix_a, 16, 16, 16, __nv_bfloat16, wmma::row_major> af;
        wmma::fragment<wmma::matrix_b, 16, 16, 16, __nv_bfloat16, wmma::col_major> bf;
        #pragma unroll
        for (int term = 0; term < 3; term++) {
            const __nv_bfloat16* sA = (term == 1) ? sA2 : sA1;
            const __nv_bfloat16* sB = (term == 2) ? sB2 : sB1;
            #pragma unroll
            for (int k0 = 0; k0 < 8; k0++) {
                wmma::load_matrix_sync(af, sA + k0 * 16, LDO);
                wmma::load_matrix_sync(bf, sB + (wid * 16) * LDO + k0 * 16, LDO);
                wmma::mma_sync(acc, af, bf, acc);
            }
        }
        wmma::store_matrix_sync(so + wid * 16, acc, 68, wmma::mem_row_major);
    }
    __syncthreads();

    #pragma unroll
    for (int idx = t; idx < 16 * 64; idx += 256) {
        const int r  = idx >> 6;
        const int cc = idx & 63;
        const int e  = col0 + cc;
        if (e < NOUT) {
            const float v = so[r * 68 + cc] + b_out[e];
            out[(e / MIX) * (NP * MIX) + (row0 + r) * MIX + (e % MIX)] = v;
        }
    }
}

// ---------------- launch ----------------
extern "C" void kernel_launch(void* const* d_in, const int* in_sizes, int n_in,
                              void* d_out, int out_size) {
    const float* xabs  = (const float*)d_in[0];
    const float* h0    = (const float*)d_in[1];
    const float* c0    = (const float*)d_in[2];
    const float* W_emb = (const float*)d_in[3];
    const float* b_emb = (const float*)d_in[4];
    const float* W_soc = (const float*)d_in[5];
    const float* b_soc = (const float*)d_in[6];
    const float* W_ih  = (const float*)d_in[7];
    const float* W_hh  = (const float*)d_in[8];
    const float* b_ih  = (const float*)d_in[9];
    const float* b_hh  = (const float*)d_in[10];
    const float* W_out = (const float*)d_in[11];
    const float* b_out = (const float*)d_in[12];
    float* out = (float*)d_out;

    cudaFuncSetAttribute(mma_P_kernel, cudaFuncAttributeMaxDynamicSharedMemorySize, SMEM_P_BYTES);

    cudaLaunchAttribute attrs[1];
    attrs[0].id = cudaLaunchAttributeProgrammaticStreamSerialization;
    attrs[0].val.programmaticStreamSerializationAllowed = 1;

    // K1: mma_P (head, normal launch)
    mma_P_kernel<<<dim3(8, 32), 256, SMEM_P_BYTES>>>(h0, W_soc);

    // K2: scatter (classify overlaps mma_P tail; wait; gather)
    {
        cudaLaunchConfig_t cfg = {};
        cfg.gridDim = dim3(NP, 1, 1);
        cfg.blockDim = dim3(512, 1, 1);
        cfg.stream = 0;
        cfg.attrs = attrs;
        cfg.numAttrs = 1;
        cudaLaunchKernelEx(&cfg, scatter_kernel, xabs, b_soc);
    }
    // K3: gates_pre (no leading wait -> concurrent with gather; trailing wait)
    {
        cudaLaunchConfig_t cfg = {};
        cfg.gridDim = dim3(16, 8, 1);
        cfg.blockDim = dim3(256, 1, 1);
        cfg.stream = 0;
        cfg.attrs = attrs;
        cfg.numAttrs = 1;
        cudaLaunchKernelEx(&cfg, gates_pre_kernel, xabs, h0, W_emb, b_emb, W_ih, W_hh, b_ih, b_hh);
    }
    // K4: gates_post + LSTM (K=64 critical-path GEMM)
    {
        cudaLaunchConfig_t cfg = {};
        cfg.gridDim = dim3(16, 8, 1);
        cfg.blockDim = dim3(256, 1, 1);
        cfg.stream = 0;
        cfg.attrs = attrs;
        cfg.numAttrs = 1;
        cudaLaunchKernelEx(&cfg, gates_post_kernel, W_ih, c0);
    }
    // K5: output projection
    {
        cudaLaunchConfig_t cfg = {};
        cfg.gridDim = dim3(64, 2, 1);
        cfg.blockDim = dim3(256, 1, 1);
        cfg.stream = 0;
        cfg.attrs = attrs;
        cfg.numAttrs = 1;
        cudaLaunchKernelEx(&cfg, out_kernel, W_out, b_out, out);
    }
}

// round 15
// speedup vs baseline: 1.2654x; 1.1031x over previous
#include <cuda_runtime.h>
#include <cuda_bf16.h>
#include <mma.h>
#include <math.h>
#include <stdint.h>

using namespace nvcuda;

#define NP     1024
#define EMBD   64
#define HID    128
#define NCELL  64
#define PN     4096     // NCELL * EMBD
#define KX     256      // [emb(64) | pool(64) | h0(128)]
#define MIX    20
#define NOUT   120

// ---------------- device scratch (static, no allocations) ----------------
__device__ float g_P[NP * PN];        // 16 MB
__device__ float g_X[NP * KX];        // 1 MB
__device__ float g_h[NP * HID];       // 0.5 MB

__device__ __forceinline__ float sigm(float x) { return 1.0f / (1.0f + expf(-x)); }

#define PDL_TRIGGER() asm volatile("griddepcontrol.launch_dependents;" ::: "memory")
#define PDL_WAIT()    asm volatile("griddepcontrol.wait;" ::: "memory")

__device__ __forceinline__ void split_store(__nv_bfloat16* d1, __nv_bfloat16* d2, float4 v) {
    __nv_bfloat162 h1a, h1b, h2a, h2b;
    h1a.x = __float2bfloat16(v.x); h2a.x = __float2bfloat16(v.x - __bfloat162float(h1a.x));
    h1a.y = __float2bfloat16(v.y); h2a.y = __float2bfloat16(v.y - __bfloat162float(h1a.y));
    h1b.x = __float2bfloat16(v.z); h2b.x = __float2bfloat16(v.z - __bfloat162float(h1b.x));
    h1b.y = __float2bfloat16(v.w); h2b.y = __float2bfloat16(v.w - __bfloat162float(h1b.y));
    *(__nv_bfloat162*)(d1)     = h1a;
    *(__nv_bfloat162*)(d1 + 2) = h1b;
    *(__nv_bfloat162*)(d2)     = h2a;
    *(__nv_bfloat162*)(d2 + 2) = h2b;
}

// ============ K1: WMMA bf16 P-GEMM (validated 39.4us body) ============
#define LDP 136
#define TILEP (128 * LDP)
#define SMEM_P_BYTES (4 * TILEP * 2)

__global__ __launch_bounds__(256, 1) void mma_P_kernel(const float* __restrict__ h0,
                                                       const float* __restrict__ Wsoc) {
    extern __shared__ __align__(16) __nv_bfloat16 smemP[];
    __nv_bfloat16* sA1 = smemP;
    __nv_bfloat16* sA2 = smemP + TILEP;
    __nv_bfloat16* sB1 = smemP + 2 * TILEP;
    __nv_bfloat16* sB2 = smemP + 3 * TILEP;

    const int t   = threadIdx.x;
    const int wid = t >> 5;
    const int warp_m = wid & 1;
    const int warp_n = wid >> 1;
    const int row0 = blockIdx.x * 128;
    const int col0 = blockIdx.y * 128;

    if (t == 0) PDL_TRIGGER();

    #pragma unroll
    for (int i = t; i < 4096; i += 256) {
        const int row = i >> 5, k4 = i & 31;
        const float4 v = *(const float4*)&h0[(row0 + row) * HID + k4 * 4];
        split_store(sA1 + row * LDP + k4 * 4, sA2 + row * LDP + k4 * 4, v);
    }
    #pragma unroll
    for (int i = t; i < 4096; i += 256) {
        const int row = i >> 5, k4 = i & 31;
        const int ce = col0 + row;
        const int e = ce & 63, c = ce >> 6;
        const float4 v = *(const float4*)&Wsoc[e * (NCELL * HID) + c * HID + k4 * 4];
        split_store(sB1 + row * LDP + k4 * 4, sB2 + row * LDP + k4 * 4, v);
    }
    __syncthreads();

    wmma::fragment<wmma::accumulator, 16, 16, 16, float> acc[4][2];
    #pragma unroll
    for (int i = 0; i < 4; i++)
        #pragma unroll
        for (int j = 0; j < 2; j++)
            wmma::fill_fragment(acc[i][j], 0.0f);

    wmma::fragment<wmma::matrix_a, 16, 16, 16, __nv_bfloat16, wmma::row_major> af;
    wmma::fragment<wmma::matrix_b, 16, 16, 16, __nv_bfloat16, wmma::col_major> bf[2];

    #pragma unroll
    for (int term = 0; term < 3; term++) {
        const __nv_bfloat16* sA = (term == 1) ? sA2 : sA1;
        const __nv_bfloat16* sB = (term == 2) ? sB2 : sB1;
        #pragma unroll
        for (int k0 = 0; k0 < 8; k0++) {
            #pragma unroll
            for (int j = 0; j < 2; j++)
                wmma::load_matrix_sync(bf[j], sB + (warp_n * 32 + j * 16) * LDP + k0 * 16, LDP);
            #pragma unroll
            for (int i = 0; i < 4; i++) {
                wmma::load_matrix_sync(af, sA + (warp_m * 64 + i * 16) * LDP + k0 * 16, LDP);
                wmma::mma_sync(acc[i][0], af, bf[0], acc[i][0]);
                wmma::mma_sync(acc[i][1], af, bf[1], acc[i][1]);
            }
        }
    }

    #pragma unroll
    for (int i = 0; i < 4; i++)
        #pragma unroll
        for (int j = 0; j < 2; j++) {
            float* dst = g_P + (size_t)(row0 + warp_m * 64 + i * 16) * PN
                             + col0 + warp_n * 32 + j * 16;
            wmma::store_matrix_sync(dst, acc[i][j], PN, wmma::mem_row_major);
        }
}

// ============ K2: classify + gather (R11 body; gather vectorized to float4) ============
__global__ __launch_bounds__(512) void scatter_kernel(const float* __restrict__ xabs,
                                                      const float* __restrict__ h0,
                                                      const float* __restrict__ W_emb,
                                                      const float* __restrict__ b_emb,
                                                      const float* __restrict__ b_soc) {
    __shared__ float sx[NP];
    __shared__ float sy[NP];
    __shared__ int   slist[NP];
    __shared__ int   wcnt[16];
    __shared__ float sred[32][64];

    const int n = blockIdx.x;
    const int t = threadIdx.x;
    const int w = t >> 5;
    const int lane = t & 31;

    if (t == 0) PDL_TRIGGER();

    for (int i = t; i < NP; i += 512) {
        const float2 v = ((const float2*)xabs)[i];
        sx[i] = v.x;
        sy[i] = v.y;
    }
    __syncthreads();

    const float wl = sx[n] - 0.2f;
    const float bl = sy[n] - 0.2f;

    int cells[2];
    unsigned masks[2];
    int cnt = 0;
    #pragma unroll
    for (int j = 0; j < 2; j++) {
        const int m = w * 64 + j * 32 + lane;
        const float dx = sx[m] - wl;
        const float dy = sy[m] - bl;
        int cell = -1;
        if (dx >= 0.0f && dx < 0.4f && dy >= 0.0f && dy < 0.4f && m != n) {
            const int cx = (int)floorf(__fmul_rn(__fdiv_rn(dx, 0.4f), 8.0f));
            const int cy = (int)floorf(__fmul_rn(__fdiv_rn(dy, 0.4f), 8.0f));
            if (cx >= 0 && cx < 8 && cy >= 0 && cy < 8) cell = cx + cy * 8;
        }
        cells[j] = (cell >= 0) ? (m * PN + cell * EMBD) : -1;
        masks[j] = __ballot_sync(0xFFFFFFFFu, cell >= 0);
        cnt += __popc(masks[j]);
    }
    if (lane == 0) wcnt[w] = cnt;

    // independent work
    if (t < 128) {
        g_X[n * KX + 128 + t] = h0[n * HID + t];
    } else if (t < 192) {
        const int e2 = t - 128;
        const float e = sx[n] * W_emb[2 * e2] + sy[n] * W_emb[2 * e2 + 1] + b_emb[e2];
        g_X[n * KX + e2] = fmaxf(e, 0.0f);
    }
    __syncthreads();

    int base = 0, tot = 0;
    #pragma unroll
    for (int ww = 0; ww < 16; ww++) {
        if (ww < w) base += wcnt[ww];
        tot += wcnt[ww];
    }
    #pragma unroll
    for (int j = 0; j < 2; j++) {
        if (cells[j] >= 0) {
            slist[base + __popc(masks[j] & ((1u << lane) - 1u))] = cells[j];
        }
        base += __popc(masks[j]);
    }
    __syncthreads();

    PDL_WAIT();   // g_P must be complete before the gather

    // gather (vectorized): 32 slots x 16 threads, each thread owns a float4 of e.
    // 2 independent accumulation chains (stride 64 rows).
    const int slot = t >> 4;          // 0..31
    const int e4   = (t & 15) * 4;    // float4 base within 64
    float4 s0 = make_float4(0.f, 0.f, 0.f, 0.f);
    float4 s1 = make_float4(0.f, 0.f, 0.f, 0.f);
    int i = slot;
    for (; i + 64 <= tot; i += 64) {
        const float4 v0 = *(const float4*)(g_P + (size_t)slist[i]      + e4);
        const float4 v1 = *(const float4*)(g_P + (size_t)slist[i + 32] + e4);
        s0.x += v0.x; s0.y += v0.y; s0.z += v0.z; s0.w += v0.w;
        s1.x += v1.x; s1.y += v1.y; s1.z += v1.z; s1.w += v1.w;
    }
    for (; i < tot; i += 32) {
        const float4 v = *(const float4*)(g_P + (size_t)slist[i] + e4);
        s0.x += v.x; s0.y += v.y; s0.z += v.z; s0.w += v.w;
    }
    sred[slot][e4]     = s0.x + s1.x;
    sred[slot][e4 + 1] = s0.y + s1.y;
    sred[slot][e4 + 2] = s0.z + s1.z;
    sred[slot][e4 + 3] = s0.w + s1.w;
    __syncthreads();

    if (t < 64) {
        float s = b_soc[t];
        #pragma unroll
        for (int sl = 0; sl < 32; sl++) s += sred[sl][t];
        g_X[n * KX + 64 + t] = fmaxf(s, 0.0f);
    }
}

// ============ K3: WMMA gates GEMM + LSTM (validated R11 body) ============
#define LDG2  264
#define TILEG (64 * LDG2)
#define SMEM_G_BYTES (4 * TILEG * 2 + 64 * 68 * 4)

__global__ __launch_bounds__(256, 1) void gates_lstm_kernel(const float* __restrict__ W_ih,
                                                            const float* __restrict__ W_hh,
                                                            const float* __restrict__ b_ih,
                                                            const float* __restrict__ b_hh,
                                                            const float* __restrict__ c0) {
    extern __shared__ __align__(16) __nv_bfloat16 smemG[];
    __nv_bfloat16* sA1 = smemG;
    __nv_bfloat16* sA2 = smemG + TILEG;
    __nv_bfloat16* sB1 = smemG + 2 * TILEG;
    __nv_bfloat16* sB2 = smemG + 3 * TILEG;
    float* sg = (float*)(smemG + 4 * TILEG);

    const int row0 = blockIdx.x * 64;
    const int d0   = blockIdx.y * 16;
    const int t   = threadIdx.x;
    const int wid = t >> 5;
    const int warp_m = wid & 3;
    const int warp_n = wid >> 2;

    if (t == 0) PDL_TRIGGER();

    #pragma unroll
    for (int i = t; i < 4096; i += 256) {
        const int cc = i >> 6, k4 = i & 63;
        const int wrow = (cc >> 4) * 128 + d0 + (cc & 15);
        const float4 v = (k4 < 32) ? *(const float4*)&W_ih[wrow * 128 + k4 * 4]
                                   : *(const float4*)&W_hh[wrow * 128 + (k4 - 32) * 4];
        split_store(sB1 + cc * LDG2 + k4 * 4, sB2 + cc * LDG2 + k4 * 4, v);
    }

    PDL_WAIT();

    #pragma unroll
    for (int i = t; i < 4096; i += 256) {
        const int row = i >> 6, k4 = i & 63;
        const float4 v = *(const float4*)&g_X[(row0 + row) * KX + k4 * 4];
        split_store(sA1 + row * LDG2 + k4 * 4, sA2 + row * LDG2 + k4 * 4, v);
    }
    __syncthreads();

    wmma::fragment<wmma::accumulator, 16, 16, 16, float> acc[2];
    wmma::fill_fragment(acc[0], 0.0f);
    wmma::fill_fragment(acc[1], 0.0f);
    wmma::fragment<wmma::matrix_a, 16, 16, 16, __nv_bfloat16, wmma::row_major> af;
    wmma::fragment<wmma::matrix_b, 16, 16, 16, __nv_bfloat16, wmma::col_major> bf[2];

    #pragma unroll
    for (int term = 0; term < 3; term++) {
        const __nv_bfloat16* sA = (term == 1) ? sA2 : sA1;
        const __nv_bfloat16* sB = (term == 2) ? sB2 : sB1;
        #pragma unroll
        for (int k0 = 0; k0 < 16; k0++) {
            wmma::load_matrix_sync(af, sA + (warp_m * 16) * LDG2 + k0 * 16, LDG2);
            #pragma unroll
            for (int j = 0; j < 2; j++) {
                wmma::load_matrix_sync(bf[j], sB + (warp_n * 32 + j * 16) * LDG2 + k0 * 16, LDG2);
                wmma::mma_sync(acc[j], af, bf[j], acc[j]);
            }
        }
    }

    #pragma unroll
    for (int j = 0; j < 2; j++)
        wmma::store_matrix_sync(sg + (warp_m * 16) * 68 + warp_n * 32 + j * 16,
                                acc[j], 68, wmma::mem_row_major);
    __syncthreads();

    #pragma unroll
    for (int idx = t; idx < 1024; idx += 256) {
        const int rl = idx >> 4;
        const int dd = idx & 15;
        const int d = d0 + dd;
        const float ig = sg[rl * 68 + dd]      + b_ih[d]       + b_hh[d];
        const float fg = sg[rl * 68 + 16 + dd] + b_ih[128 + d] + b_hh[128 + d];
        const float gg = sg[rl * 68 + 32 + dd] + b_ih[256 + d] + b_hh[256 + d];
        const float og = sg[rl * 68 + 48 + dd] + b_ih[384 + d] + b_hh[384 + d];
        const int n = row0 + rl;
        const float c = sigm(fg) * c0[n * HID + d] + sigm(ig) * tanhf(gg);
        g_h[n * HID + d] = sigm(og) * tanhf(c);
    }
}

// ============ K4: WMMA output projection (validated body) ============
#define LDO 136

__global__ __launch_bounds__(256) void out_kernel(const float* __restrict__ W_out,
                                                  const float* __restrict__ b_out,
                                                  float* __restrict__ out) {
    __shared__ __align__(16) __nv_bfloat16 sA1[16 * LDO];
    __shared__ __align__(16) __nv_bfloat16 sA2[16 * LDO];
    __shared__ __align__(16) __nv_bfloat16 sB1[64 * LDO];
    __shared__ __align__(16) __nv_bfloat16 sB2[64 * LDO];
    __shared__ float so[16 * 68];

    const int row0 = blockIdx.x * 16;
    const int col0 = blockIdx.y * 64;
    const int t   = threadIdx.x;
    const int wid = t >> 5;

    #pragma unroll
    for (int i = t; i < 2048; i += 256) {
        const int ee = i >> 5, k4 = i & 31;
        const int eg = col0 + ee;
        const float4 v = (eg < NOUT) ? *(const float4*)&W_out[eg * HID + k4 * 4]
                                     : make_float4(0.f, 0.f, 0.f, 0.f);
        split_store(sB1 + ee * LDO + k4 * 4, sB2 + ee * LDO + k4 * 4, v);
    }

    PDL_WAIT();

    #pragma unroll
    for (int i = t; i < 512; i += 256) {
        const int row = i >> 5, k4 = i & 31;
        const float4 v = *(const float4*)&g_h[(row0 + row) * HID + k4 * 4];
        split_store(sA1 + row * LDO + k4 * 4, sA2 + row * LDO + k4 * 4, v);
    }
    __syncthreads();

    if (wid < 4) {
        wmma::fragment<wmma::accumulator, 16, 16, 16, float> acc;
        wmma::fill_fragment(acc, 0.0f);
        wmma::fragment<wmma::matrix_a, 16, 16, 16, __nv_bfloat16, wmma::row_major> af;
        wmma::fragment<wmma::matrix_b, 16, 16, 16, __nv_bfloat16, wmma::col_major> bf;
        #pragma unroll
        for (int term = 0; term < 3; term++) {
            const __nv_bfloat16* sA = (term == 1) ? sA2 : sA1;
            const __nv_bfloat16* sB = (term == 2) ? sB2 : sB1;
            #pragma unroll
            for (int k0 = 0; k0 < 8; k0++) {
                wmma::load_matrix_sync(af, sA + k0 * 16, LDO);
                wmma::load_matrix_sync(bf, sB + (wid * 16) * LDO + k0 * 16, LDO);
                wmma::mma_sync(acc, af, bf, acc);
            }
        }
        wmma::store_matrix_sync(so + wid * 16, acc, 68, wmma::mem_row_major);
    }
    __syncthreads();

    #pragma unroll
    for (int idx = t; idx < 16 * 64; idx += 256) {
        const int r  = idx >> 6;
        const int cc = idx & 63;
        const int e  = col0 + cc;
        if (e < NOUT) {
            const float v = so[r * 68 + cc] + b_out[e];
            out[(e / MIX) * (NP * MIX) + (row0 + r) * MIX + (e % MIX)] = v;
        }
    }
}

// ---------------- launch ----------------
extern "C" void kernel_launch(void* const* d_in, const int* in_sizes, int n_in,
                              void* d_out, int out_size) {
    const float* xabs  = (const float*)d_in[0];
    const float* h0    = (const float*)d_in[1];
    const float* c0    = (const float*)d_in[2];
    const float* W_emb = (const float*)d_in[3];
    const float* b_emb = (const float*)d_in[4];
    const float* W_soc = (const float*)d_in[5];
    const float* b_soc = (const float*)d_in[6];
    const float* W_ih  = (const float*)d_in[7];
    const float* W_hh  = (const float*)d_in[8];
    const float* b_ih  = (const float*)d_in[9];
    const float* b_hh  = (const float*)d_in[10];
    const float* W_out = (const float*)d_in[11];
    const float* b_out = (const float*)d_in[12];
    float* out = (float*)d_out;

    cudaFuncSetAttribute(mma_P_kernel, cudaFuncAttributeMaxDynamicSharedMemorySize, SMEM_P_BYTES);
    cudaFuncSetAttribute(gates_lstm_kernel, cudaFuncAttributeMaxDynamicSharedMemorySize, SMEM_G_BYTES);

    // K1: mma_P (head, normal launch)
    mma_P_kernel<<<dim3(8, 32), 256, SMEM_P_BYTES>>>(h0, W_soc);

    cudaLaunchAttribute attrs[1];
    attrs[0].id = cudaLaunchAttributeProgrammaticStreamSerialization;
    attrs[0].val.programmaticStreamSerializationAllowed = 1;

    // K2: scatter (classify overlaps mma_P tail; wait; vectorized gather)
    {
        cudaLaunchConfig_t cfg = {};
        cfg.gridDim = dim3(NP, 1, 1);
        cfg.blockDim = dim3(512, 1, 1);
        cfg.stream = 0;
        cfg.attrs = attrs;
        cfg.numAttrs = 1;
        cudaLaunchKernelEx(&cfg, scatter_kernel, xabs, h0, W_emb, b_emb, b_soc);
    }
    // K3: gates + LSTM
    {
        cudaLaunchConfig_t cfg = {};
        cfg.gridDim = dim3(16, 8, 1);
        cfg.blockDim = dim3(256, 1, 1);
        cfg.dynamicSmemBytes = SMEM_G_BYTES;
        cfg.stream = 0;
        cfg.attrs = attrs;
        cfg.numAttrs = 1;
        cudaLaunchKernelEx(&cfg, gates_lstm_kernel, W_ih, W_hh, b_ih, b_hh, c0);
    }
    // K4: output projection
    {
        cudaLaunchConfig_t cfg = {};
        cfg.gridDim = dim3(64, 2, 1);
        cfg.blockDim = dim3(256, 1, 1);
        cfg.stream = 0;
        cfg.attrs = attrs;
        cfg.numAttrs = 1;
        cudaLaunchKernelEx(&cfg, out_kernel, W_out, b_out, out);
    }
}

// round 16
// speedup vs baseline: 1.2665x; 1.0008x over previous
#include <cuda_runtime.h>
#include <cuda_bf16.h>
#include <mma.h>
#include <math.h>
#include <stdint.h>

using namespace nvcuda;

#define NP     1024
#define EMBD   64
#define HID    128
#define NCELL  64
#define PN     4096     // NCELL * EMBD
#define KX     256      // [emb(64) | pool(64) | h0(128)]
#define MIX    20
#define NOUT   120

// ---------------- device scratch (static, no allocations) ----------------
__device__ float g_P[NP * PN];        // 16 MB
__device__ float g_X[NP * KX];        // 1 MB
__device__ float g_h[NP * HID];       // 0.5 MB

__device__ __forceinline__ float sigm(float x) { return 1.0f / (1.0f + expf(-x)); }

#define PDL_TRIGGER() asm volatile("griddepcontrol.launch_dependents;" ::: "memory")
#define PDL_WAIT()    asm volatile("griddepcontrol.wait;" ::: "memory")

__device__ __forceinline__ void split_store(__nv_bfloat16* d1, __nv_bfloat16* d2, float4 v) {
    __nv_bfloat162 h1a, h1b, h2a, h2b;
    h1a.x = __float2bfloat16(v.x); h2a.x = __float2bfloat16(v.x - __bfloat162float(h1a.x));
    h1a.y = __float2bfloat16(v.y); h2a.y = __float2bfloat16(v.y - __bfloat162float(h1a.y));
    h1b.x = __float2bfloat16(v.z); h2b.x = __float2bfloat16(v.z - __bfloat162float(h1b.x));
    h1b.y = __float2bfloat16(v.w); h2b.y = __float2bfloat16(v.w - __bfloat162float(h1b.y));
    *(__nv_bfloat162*)(d1)     = h1a;
    *(__nv_bfloat162*)(d1 + 2) = h1b;
    *(__nv_bfloat162*)(d2)     = h2a;
    *(__nv_bfloat162*)(d2 + 2) = h2b;
}

// ============ K1: WMMA bf16 P-GEMM, 128x256 per CTA (single wave of 128 CTAs) ============
// A (h0 tile) loaded+split once; two 128-col B halves processed through reused buffers.
#define LDP 136
#define TILEP (128 * LDP)
#define SMEM_P_BYTES (4 * TILEP * 2)

__global__ __launch_bounds__(256, 1) void mma_P_kernel(const float* __restrict__ h0,
                                                       const float* __restrict__ Wsoc) {
    extern __shared__ __align__(16) __nv_bfloat16 smemP[];
    __nv_bfloat16* sA1 = smemP;
    __nv_bfloat16* sA2 = smemP + TILEP;
    __nv_bfloat16* sB1 = smemP + 2 * TILEP;
    __nv_bfloat16* sB2 = smemP + 3 * TILEP;

    const int t   = threadIdx.x;
    const int wid = t >> 5;
    const int warp_m = wid & 1;
    const int warp_n = wid >> 1;
    const int row0    = blockIdx.x * 128;
    const int colbase = blockIdx.y * 256;

    if (t == 0) PDL_TRIGGER();

    // A tile: load + split ONCE
    #pragma unroll
    for (int i = t; i < 4096; i += 256) {
        const int row = i >> 5, k4 = i & 31;
        const float4 v = *(const float4*)&h0[(row0 + row) * HID + k4 * 4];
        split_store(sA1 + row * LDP + k4 * 4, sA2 + row * LDP + k4 * 4, v);
    }

    wmma::fragment<wmma::accumulator, 16, 16, 16, float> acc[4][2];
    wmma::fragment<wmma::matrix_a, 16, 16, 16, __nv_bfloat16, wmma::row_major> af;
    wmma::fragment<wmma::matrix_b, 16, 16, 16, __nv_bfloat16, wmma::col_major> bf[2];

    #pragma unroll
    for (int half = 0; half < 2; half++) {
        const int col0 = colbase + half * 128;
        if (half) __syncthreads();   // all warps done reading sB of previous half
        #pragma unroll
        for (int i = t; i < 4096; i += 256) {
            const int row = i >> 5, k4 = i & 31;
            const int ce = col0 + row;
            const int e = ce & 63, c = ce >> 6;
            const float4 v = *(const float4*)&Wsoc[e * (NCELL * HID) + c * HID + k4 * 4];
            split_store(sB1 + row * LDP + k4 * 4, sB2 + row * LDP + k4 * 4, v);
        }
        __syncthreads();

        #pragma unroll
        for (int i = 0; i < 4; i++)
            #pragma unroll
            for (int j = 0; j < 2; j++)
                wmma::fill_fragment(acc[i][j], 0.0f);

        #pragma unroll
        for (int term = 0; term < 3; term++) {
            const __nv_bfloat16* sA = (term == 1) ? sA2 : sA1;
            const __nv_bfloat16* sB = (term == 2) ? sB2 : sB1;
            #pragma unroll
            for (int k0 = 0; k0 < 8; k0++) {
                #pragma unroll
                for (int j = 0; j < 2; j++)
                    wmma::load_matrix_sync(bf[j], sB + (warp_n * 32 + j * 16) * LDP + k0 * 16, LDP);
                #pragma unroll
                for (int i = 0; i < 4; i++) {
                    wmma::load_matrix_sync(af, sA + (warp_m * 64 + i * 16) * LDP + k0 * 16, LDP);
                    wmma::mma_sync(acc[i][0], af, bf[0], acc[i][0]);
                    wmma::mma_sync(acc[i][1], af, bf[1], acc[i][1]);
                }
            }
        }

        #pragma unroll
        for (int i = 0; i < 4; i++)
            #pragma unroll
            for (int j = 0; j < 2; j++) {
                float* dst = g_P + (size_t)(row0 + warp_m * 64 + i * 16) * PN
                                 + col0 + warp_n * 32 + j * 16;
                wmma::store_matrix_sync(dst, acc[i][j], PN, wmma::mem_row_major);
            }
    }
}

// ============ K2: classify + gather (R15 body, vectorized float4 gather) ============
__global__ __launch_bounds__(512) void scatter_kernel(const float* __restrict__ xabs,
                                                      const float* __restrict__ h0,
                                                      const float* __restrict__ W_emb,
                                                      const float* __restrict__ b_emb,
                                                      const float* __restrict__ b_soc) {
    __shared__ float sx[NP];
    __shared__ float sy[NP];
    __shared__ int   slist[NP];
    __shared__ int   wcnt[16];
    __shared__ float sred[32][64];

    const int n = blockIdx.x;
    const int t = threadIdx.x;
    const int w = t >> 5;
    const int lane = t & 31;

    if (t == 0) PDL_TRIGGER();

    for (int i = t; i < NP; i += 512) {
        const float2 v = ((const float2*)xabs)[i];
        sx[i] = v.x;
        sy[i] = v.y;
    }
    __syncthreads();

    const float wl = sx[n] - 0.2f;
    const float bl = sy[n] - 0.2f;

    int cells[2];
    unsigned masks[2];
    int cnt = 0;
    #pragma unroll
    for (int j = 0; j < 2; j++) {
        const int m = w * 64 + j * 32 + lane;
        const float dx = sx[m] - wl;
        const float dy = sy[m] - bl;
        int cell = -1;
        if (dx >= 0.0f && dx < 0.4f && dy >= 0.0f && dy < 0.4f && m != n) {
            const int cx = (int)floorf(__fmul_rn(__fdiv_rn(dx, 0.4f), 8.0f));
            const int cy = (int)floorf(__fmul_rn(__fdiv_rn(dy, 0.4f), 8.0f));
            if (cx >= 0 && cx < 8 && cy >= 0 && cy < 8) cell = cx + cy * 8;
        }
        cells[j] = (cell >= 0) ? (m * PN + cell * EMBD) : -1;
        masks[j] = __ballot_sync(0xFFFFFFFFu, cell >= 0);
        cnt += __popc(masks[j]);
    }
    if (lane == 0) wcnt[w] = cnt;

    if (t < 128) {
        g_X[n * KX + 128 + t] = h0[n * HID + t];
    } else if (t < 192) {
        const int e2 = t - 128;
        const float e = sx[n] * W_emb[2 * e2] + sy[n] * W_emb[2 * e2 + 1] + b_emb[e2];
        g_X[n * KX + e2] = fmaxf(e, 0.0f);
    }
    __syncthreads();

    int base = 0, tot = 0;
    #pragma unroll
    for (int ww = 0; ww < 16; ww++) {
        if (ww < w) base += wcnt[ww];
        tot += wcnt[ww];
    }
    #pragma unroll
    for (int j = 0; j < 2; j++) {
        if (cells[j] >= 0) {
            slist[base + __popc(masks[j] & ((1u << lane) - 1u))] = cells[j];
        }
        base += __popc(masks[j]);
    }
    __syncthreads();

    PDL_WAIT();   // g_P must be complete before the gather

    const int slot = t >> 4;          // 0..31
    const int e4   = (t & 15) * 4;
    float4 s0 = make_float4(0.f, 0.f, 0.f, 0.f);
    float4 s1 = make_float4(0.f, 0.f, 0.f, 0.f);
    int i = slot;
    for (; i + 64 <= tot; i += 64) {
        const float4 v0 = *(const float4*)(g_P + (size_t)slist[i]      + e4);
        const float4 v1 = *(const float4*)(g_P + (size_t)slist[i + 32] + e4);
        s0.x += v0.x; s0.y += v0.y; s0.z += v0.z; s0.w += v0.w;
        s1.x += v1.x; s1.y += v1.y; s1.z += v1.z; s1.w += v1.w;
    }
    for (; i < tot; i += 32) {
        const float4 v = *(const float4*)(g_P + (size_t)slist[i] + e4);
        s0.x += v.x; s0.y += v.y; s0.z += v.z; s0.w += v.w;
    }
    sred[slot][e4]     = s0.x + s1.x;
    sred[slot][e4 + 1] = s0.y + s1.y;
    sred[slot][e4 + 2] = s0.z + s1.z;
    sred[slot][e4 + 3] = s0.w + s1.w;
    __syncthreads();

    if (t < 64) {
        float s = b_soc[t];
        #pragma unroll
        for (int sl = 0; sl < 32; sl++) s += sred[sl][t];
        g_X[n * KX + 64 + t] = fmaxf(s, 0.0f);
    }
}

// ============ K3: WMMA gates GEMM + LSTM (validated body) ============
#define LDG2  264
#define TILEG (64 * LDG2)
#define SMEM_G_BYTES (4 * TILEG * 2 + 64 * 68 * 4)

__global__ __launch_bounds__(256, 1) void gates_lstm_kernel(const float* __restrict__ W_ih,
                                                            const float* __restrict__ W_hh,
                                                            const float* __restrict__ b_ih,
                                                            const float* __restrict__ b_hh,
                                                            const float* __restrict__ c0) {
    extern __shared__ __align__(16) __nv_bfloat16 smemG[];
    __nv_bfloat16* sA1 = smemG;
    __nv_bfloat16* sA2 = smemG + TILEG;
    __nv_bfloat16* sB1 = smemG + 2 * TILEG;
    __nv_bfloat16* sB2 = smemG + 3 * TILEG;
    float* sg = (float*)(smemG + 4 * TILEG);

    const int row0 = blockIdx.x * 64;
    const int d0   = blockIdx.y * 16;
    const int t   = threadIdx.x;
    const int wid = t >> 5;
    const int warp_m = wid & 3;
    const int warp_n = wid >> 2;

    if (t == 0) PDL_TRIGGER();

    #pragma unroll
    for (int i = t; i < 4096; i += 256) {
        const int cc = i >> 6, k4 = i & 63;
        const int wrow = (cc >> 4) * 128 + d0 + (cc & 15);
        const float4 v = (k4 < 32) ? *(const float4*)&W_ih[wrow * 128 + k4 * 4]
                                   : *(const float4*)&W_hh[wrow * 128 + (k4 - 32) * 4];
        split_store(sB1 + cc * LDG2 + k4 * 4, sB2 + cc * LDG2 + k4 * 4, v);
    }

    PDL_WAIT();

    #pragma unroll
    for (int i = t; i < 4096; i += 256) {
        const int row = i >> 6, k4 = i & 63;
        const float4 v = *(const float4*)&g_X[(row0 + row) * KX + k4 * 4];
        split_store(sA1 + row * LDG2 + k4 * 4, sA2 + row * LDG2 + k4 * 4, v);
    }
    __syncthreads();

    wmma::fragment<wmma::accumulator, 16, 16, 16, float> acc[2];
    wmma::fill_fragment(acc[0], 0.0f);
    wmma::fill_fragment(acc[1], 0.0f);
    wmma::fragment<wmma::matrix_a, 16, 16, 16, __nv_bfloat16, wmma::row_major> af;
    wmma::fragment<wmma::matrix_b, 16, 16, 16, __nv_bfloat16, wmma::col_major> bf[2];

    #pragma unroll
    for (int term = 0; term < 3; term++) {
        const __nv_bfloat16* sA = (term == 1) ? sA2 : sA1;
        const __nv_bfloat16* sB = (term == 2) ? sB2 : sB1;
        #pragma unroll
        for (int k0 = 0; k0 < 16; k0++) {
            wmma::load_matrix_sync(af, sA + (warp_m * 16) * LDG2 + k0 * 16, LDG2);
            #pragma unroll
            for (int j = 0; j < 2; j++) {
                wmma::load_matrix_sync(bf[j], sB + (warp_n * 32 + j * 16) * LDG2 + k0 * 16, LDG2);
                wmma::mma_sync(acc[j], af, bf[j], acc[j]);
            }
        }
    }

    #pragma unroll
    for (int j = 0; j < 2; j++)
        wmma::store_matrix_sync(sg + (warp_m * 16) * 68 + warp_n * 32 + j * 16,
                                acc[j], 68, wmma::mem_row_major);
    __syncthreads();

    #pragma unroll
    for (int idx = t; idx < 1024; idx += 256) {
        const int rl = idx >> 4;
        const int dd = idx & 15;
        const int d = d0 + dd;
        const float ig = sg[rl * 68 + dd]      + b_ih[d]       + b_hh[d];
        const float fg = sg[rl * 68 + 16 + dd] + b_ih[128 + d] + b_hh[128 + d];
        const float gg = sg[rl * 68 + 32 + dd] + b_ih[256 + d] + b_hh[256 + d];
        const float og = sg[rl * 68 + 48 + dd] + b_ih[384 + d] + b_hh[384 + d];
        const int n = row0 + rl;
        const float c = sigm(fg) * c0[n * HID + d] + sigm(ig) * tanhf(gg);
        g_h[n * HID + d] = sigm(og) * tanhf(c);
    }
}

// ============ K4: WMMA output projection (validated body) ============
#define LDO 136

__global__ __launch_bounds__(256) void out_kernel(const float* __restrict__ W_out,
                                                  const float* __restrict__ b_out,
                                                  float* __restrict__ out) {
    __shared__ __align__(16) __nv_bfloat16 sA1[16 * LDO];
    __shared__ __align__(16) __nv_bfloat16 sA2[16 * LDO];
    __shared__ __align__(16) __nv_bfloat16 sB1[64 * LDO];
    __shared__ __align__(16) __nv_bfloat16 sB2[64 * LDO];
    __shared__ float so[16 * 68];

    const int row0 = blockIdx.x * 16;
    const int col0 = blockIdx.y * 64;
    const int t   = threadIdx.x;
    const int wid = t >> 5;

    #pragma unroll
    for (int i = t; i < 2048; i += 256) {
        const int ee = i >> 5, k4 = i & 31;
        const int eg = col0 + ee;
        const float4 v = (eg < NOUT) ? *(const float4*)&W_out[eg * HID + k4 * 4]
                                     : make_float4(0.f, 0.f, 0.f, 0.f);
        split_store(sB1 + ee * LDO + k4 * 4, sB2 + ee * LDO + k4 * 4, v);
    }

    PDL_WAIT();

    #pragma unroll
    for (int i = t; i < 512; i += 256) {
        const int row = i >> 5, k4 = i & 31;
        const float4 v = *(const float4*)&g_h[(row0 + row) * HID + k4 * 4];
        split_store(sA1 + row * LDO + k4 * 4, sA2 + row * LDO + k4 * 4, v);
    }
    __syncthreads();

    if (wid < 4) {
        wmma::fragment<wmma::accumulator, 16, 16, 16, float> acc;
        wmma::fill_fragment(acc, 0.0f);
        wmma::fragment<wmma::matrix_a, 16, 16, 16, __nv_bfloat16, wmma::row_major> af;
        wmma::fragment<wmma::matrix_b, 16, 16, 16, __nv_bfloat16, wmma::col_major> bf;
        #pragma unroll
        for (int term = 0; term < 3; term++) {
            const __nv_bfloat16* sA = (term == 1) ? sA2 : sA1;
            const __nv_bfloat16* sB = (term == 2) ? sB2 : sB1;
            #pragma unroll
            for (int k0 = 0; k0 < 8; k0++) {
                wmma::load_matrix_sync(af, sA + k0 * 16, LDO);
                wmma::load_matrix_sync(bf, sB + (wid * 16) * LDO + k0 * 16, LDO);
                wmma::mma_sync(acc, af, bf, acc);
            }
        }
        wmma::store_matrix_sync(so + wid * 16, acc, 68, wmma::mem_row_major);
    }
    __syncthreads();

    #pragma unroll
    for (int idx = t; idx < 16 * 64; idx += 256) {
        const int r  = idx >> 6;
        const int cc = idx & 63;
        const int e  = col0 + cc;
        if (e < NOUT) {
            const float v = so[r * 68 + cc] + b_out[e];
            out[(e / MIX) * (NP * MIX) + (row0 + r) * MIX + (e % MIX)] = v;
        }
    }
}

// ---------------- launch ----------------
extern "C" void kernel_launch(void* const* d_in, const int* in_sizes, int n_in,
                              void* d_out, int out_size) {
    const float* xabs  = (const float*)d_in[0];
    const float* h0    = (const float*)d_in[1];
    const float* c0    = (const float*)d_in[2];
    const float* W_emb = (const float*)d_in[3];
    const float* b_emb = (const float*)d_in[4];
    const float* W_soc = (const float*)d_in[5];
    const float* b_soc = (const float*)d_in[6];
    const float* W_ih  = (const float*)d_in[7];
    const float* W_hh  = (const float*)d_in[8];
    const float* b_ih  = (const float*)d_in[9];
    const float* b_hh  = (const float*)d_in[10];
    const float* W_out = (const float*)d_in[11];
    const float* b_out = (const float*)d_in[12];
    float* out = (float*)d_out;

    cudaFuncSetAttribute(mma_P_kernel, cudaFuncAttributeMaxDynamicSharedMemorySize, SMEM_P_BYTES);
    cudaFuncSetAttribute(gates_lstm_kernel, cudaFuncAttributeMaxDynamicSharedMemorySize, SMEM_G_BYTES);

    // K1: mma_P — single wave of 128 CTAs (8 row-tiles x 16 col-supertiles)
    mma_P_kernel<<<dim3(8, 16), 256, SMEM_P_BYTES>>>(h0, W_soc);

    cudaLaunchAttribute attrs[1];
    attrs[0].id = cudaLaunchAttributeProgrammaticStreamSerialization;
    attrs[0].val.programmaticStreamSerializationAllowed = 1;

    // K2: scatter (classify overlaps mma_P; wait; vectorized gather)
    {
        cudaLaunchConfig_t cfg = {};
        cfg.gridDim = dim3(NP, 1, 1);
        cfg.blockDim = dim3(512, 1, 1);
        cfg.stream = 0;
        cfg.attrs = attrs;
        cfg.numAttrs = 1;
        cudaLaunchKernelEx(&cfg, scatter_kernel, xabs, h0, W_emb, b_emb, b_soc);
    }
    // K3: gates + LSTM
    {
        cudaLaunchConfig_t cfg = {};
        cfg.gridDim = dim3(16, 8, 1);
        cfg.blockDim = dim3(256, 1, 1);
        cfg.dynamicSmemBytes = SMEM_G_BYTES;
        cfg.stream = 0;
        cfg.attrs = attrs;
        cfg.numAttrs = 1;
        cudaLaunchKernelEx(&cfg, gates_lstm_kernel, W_ih, W_hh, b_ih, b_hh, c0);
    }
    // K4: output projection
    {
        cudaLaunchConfig_t cfg = {};
        cfg.gridDim = dim3(64, 2, 1);
        cfg.blockDim = dim3(256, 1, 1);
        cfg.stream = 0;
        cfg.attrs = attrs;
        cfg.numAttrs = 1;
        cudaLaunchKernelEx(&cfg, out_kernel, W_out, b_out, out);
    }
}